// round 9
// baseline (speedup 1.0000x reference)
#include <cuda_runtime.h>

#define BATCHES 4
#define MBOX    128
#define TPB     256
#define PPT     4
#define GRIDW   32
#define NCELL   (GRIDW * GRIDW)
#define CAP     32    // smem list cap; overflow handled by brute-force fallback
#define BOXF    7     // floats per box

__global__ __launch_bounds__(TPB)
void pib_fused(const float* __restrict__ pts,
               const float* __restrict__ boxes,
               float* __restrict__ out,
               int N)
{
    // Preprocessed boxes:
    //   sA[m] = (cx, cy, cos, sin)
    //   sB[m] = (hx, hy, cz, hz)
    __shared__ float4 sA[MBOX];
    __shared__ float4 sB[MBOX];
    __shared__ int    cnt[NCELL];
    __shared__ unsigned char lst[NCELL][CAP];
    __shared__ float  sRaw[MBOX * BOXF];          // coalesced staging (3.5 KB)

    const int bpb = gridDim.x / BATCHES;     // 64
    const int b   = blockIdx.x / bpb;
    const int blk = blockIdx.x % bpb;
    const int t   = threadIdx.x;

    // Zero counters (one STS.128 per thread) + coalesced box staging.
    {
        int4 z = make_int4(0, 0, 0, 0);
        reinterpret_cast<int4*>(cnt)[t] = z;      // NCELL/4 == TPB
        const float* src = boxes + (size_t)b * MBOX * BOXF;
        #pragma unroll
        for (int i = t; i < MBOX * BOXF; i += TPB)
            sRaw[i] = src[i];
    }
    __syncthreads();

    const float inv_cell = (float)GRIDW / 100.0f;   // 0.32
    const float org      = -50.0f;

    // ---- build: one thread per box, reading staged smem ----
    if (t < MBOX) {
        const float* bx = &sRaw[t * BOXF];
        float cx = bx[0], cy = bx[1], cz = bx[2];
        float hx = 0.5f * bx[3], hy = 0.5f * bx[4], hz = 0.5f * bx[5];
        float s, c;
        __sincosf(bx[6], &s, &c);
        sA[t] = make_float4(cx, cy, c, s);
        sB[t] = make_float4(hx, hy, cz, hz);

        // Conservative AABB of the rotated footprint, inflated well past
        // any fp rounding slack in the in-box test (~1e-5).
        float ac = fabsf(c), as = fabsf(s);
        float ex = hx * ac + hy * as + 1e-3f;
        float ey = hx * as + hy * ac + 1e-3f;

        int xlo = min(max((int)floorf((cx - ex - org) * inv_cell), 0), GRIDW - 1);
        int xhi = min(max((int)floorf((cx + ex - org) * inv_cell), 0), GRIDW - 1);
        int ylo = min(max((int)floorf((cy - ey - org) * inv_cell), 0), GRIDW - 1);
        int yhi = min(max((int)floorf((cy + ey - org) * inv_cell), 0), GRIDW - 1);

        for (int yy = ylo; yy <= yhi; ++yy)
            for (int xx = xlo; xx <= xhi; ++xx) {
                int cell = yy * GRIDW + xx;
                int p = atomicAdd(&cnt[cell], 1);
                if (p < CAP) lst[cell][p] = (unsigned char)t;
            }
    }
    __syncthreads();

    // ---- query: four points per thread, interleaved, guard-free ----
    // Safety: evaluating the exact test against ANY box index is correct-
    // neutral (a true hit implies the box is in the point's cell list, so
    // min() is unchanged; a false hit contributes nothing). Hence entries
    // past a cell's count may be garbage; we only clamp to &127 for bounds.
    const int i0 = (blk * TPB + t) * PPT;
    const float4* p4 = reinterpret_cast<const float4*>(pts + ((size_t)b * N + i0) * 3);
    float4 qa = p4[0], qb = p4[1], qc = p4[2];
    float x0 = qa.x, y0 = qa.y, z0 = qa.z;
    float x1 = qa.w, y1 = qb.x, z1 = qb.y;
    float x2 = qb.z, y2 = qb.w, z2 = qc.x;
    float x3 = qc.y, y3 = qc.z, z3 = qc.w;

    int cell0, cell1, cell2, cell3;
    {
        int ix, iy;
        ix = min(max((int)floorf((x0 - org) * inv_cell), 0), GRIDW - 1);
        iy = min(max((int)floorf((y0 - org) * inv_cell), 0), GRIDW - 1);
        cell0 = iy * GRIDW + ix;
        ix = min(max((int)floorf((x1 - org) * inv_cell), 0), GRIDW - 1);
        iy = min(max((int)floorf((y1 - org) * inv_cell), 0), GRIDW - 1);
        cell1 = iy * GRIDW + ix;
        ix = min(max((int)floorf((x2 - org) * inv_cell), 0), GRIDW - 1);
        iy = min(max((int)floorf((y2 - org) * inv_cell), 0), GRIDW - 1);
        cell2 = iy * GRIDW + ix;
        ix = min(max((int)floorf((x3 - org) * inv_cell), 0), GRIDW - 1);
        iy = min(max((int)floorf((y3 - org) * inv_cell), 0), GRIDW - 1);
        cell3 = iy * GRIDW + ix;
    }
    int n0 = cnt[cell0], n1 = cnt[cell1], n2 = cnt[cell2], n3 = cnt[cell3];

    int l0 = (n0 <= CAP) ? n0 : 0;
    int l1 = (n1 <= CAP) ? n1 : 0;
    int l2 = (n2 <= CAP) ? n2 : 0;
    int l3 = (n3 <= CAP) ? n3 : 0;
    int nmax = (max(max(l0, l1), max(l2, l3)) + 3) & ~3;   // <= CAP, mult of 4

    int best0 = MBOX, best1 = MBOX, best2 = MBOX, best3 = MBOX;

    for (int j = 0; j < nmax; j += 4) {
        unsigned int u0 = *reinterpret_cast<const unsigned int*>(&lst[cell0][j]);
        unsigned int u1 = *reinterpret_cast<const unsigned int*>(&lst[cell1][j]);
        unsigned int u2 = *reinterpret_cast<const unsigned int*>(&lst[cell2][j]);
        unsigned int u3 = *reinterpret_cast<const unsigned int*>(&lst[cell3][j]);
        #pragma unroll
        for (int k = 0; k < 4; ++k) {
            {
                int m = (u0 >> (8 * k)) & 127;
                float4 A = sA[m]; float4 Bv = sB[m];
                float dx = x0 - A.x, dy = y0 - A.y, dz = z0 - Bv.z;
                float lx = dx * A.z + dy * A.w;
                float ly = dy * A.z - dx * A.w;
                bool in = (fabsf(lx) <= Bv.x) & (fabsf(ly) <= Bv.y) & (fabsf(dz) <= Bv.w);
                best0 = min(best0, in ? m : MBOX);
            }
            {
                int m = (u1 >> (8 * k)) & 127;
                float4 A = sA[m]; float4 Bv = sB[m];
                float dx = x1 - A.x, dy = y1 - A.y, dz = z1 - Bv.z;
                float lx = dx * A.z + dy * A.w;
                float ly = dy * A.z - dx * A.w;
                bool in = (fabsf(lx) <= Bv.x) & (fabsf(ly) <= Bv.y) & (fabsf(dz) <= Bv.w);
                best1 = min(best1, in ? m : MBOX);
            }
            {
                int m = (u2 >> (8 * k)) & 127;
                float4 A = sA[m]; float4 Bv = sB[m];
                float dx = x2 - A.x, dy = y2 - A.y, dz = z2 - Bv.z;
                float lx = dx * A.z + dy * A.w;
                float ly = dy * A.z - dx * A.w;
                bool in = (fabsf(lx) <= Bv.x) & (fabsf(ly) <= Bv.y) & (fabsf(dz) <= Bv.w);
                best2 = min(best2, in ? m : MBOX);
            }
            {
                int m = (u3 >> (8 * k)) & 127;
                float4 A = sA[m]; float4 Bv = sB[m];
                float dx = x3 - A.x, dy = y3 - A.y, dz = z3 - Bv.z;
                float lx = dx * A.z + dy * A.w;
                float ly = dy * A.z - dx * A.w;
                bool in = (fabsf(lx) <= Bv.x) & (fabsf(ly) <= Bv.y) & (fabsf(dz) <= Bv.w);
                best3 = min(best3, in ? m : MBOX);
            }
        }
    }

    // Structural overflow fallback: test every box (never skips a hit).
    if ((n0 > CAP) | (n1 > CAP) | (n2 > CAP) | (n3 > CAP)) {
        for (int m = 0; m < MBOX; ++m) {
            float4 A = sA[m]; float4 Bv = sB[m];
            if (n0 > CAP) {
                float dx = x0 - A.x, dy = y0 - A.y, dz = z0 - Bv.z;
                float lx = dx * A.z + dy * A.w;
                float ly = dy * A.z - dx * A.w;
                bool in = (fabsf(lx) <= Bv.x) & (fabsf(ly) <= Bv.y) & (fabsf(dz) <= Bv.w);
                best0 = min(best0, in ? m : MBOX);
            }
            if (n1 > CAP) {
                float dx = x1 - A.x, dy = y1 - A.y, dz = z1 - Bv.z;
                float lx = dx * A.z + dy * A.w;
                float ly = dy * A.z - dx * A.w;
                bool in = (fabsf(lx) <= Bv.x) & (fabsf(ly) <= Bv.y) & (fabsf(dz) <= Bv.w);
                best1 = min(best1, in ? m : MBOX);
            }
            if (n2 > CAP) {
                float dx = x2 - A.x, dy = y2 - A.y, dz = z2 - Bv.z;
                float lx = dx * A.z + dy * A.w;
                float ly = dy * A.z - dx * A.w;
                bool in = (fabsf(lx) <= Bv.x) & (fabsf(ly) <= Bv.y) & (fabsf(dz) <= Bv.w);
                best2 = min(best2, in ? m : MBOX);
            }
            if (n3 > CAP) {
                float dx = x3 - A.x, dy = y3 - A.y, dz = z3 - Bv.z;
                float lx = dx * A.z + dy * A.w;
                float ly = dy * A.z - dx * A.w;
                bool in = (fabsf(lx) <= Bv.x) & (fabsf(ly) <= Bv.y) & (fabsf(dz) <= Bv.w);
                best3 = min(best3, in ? m : MBOX);
            }
        }
    }

    float4 o = make_float4((best0 == MBOX) ? -1.0f : (float)best0,
                           (best1 == MBOX) ? -1.0f : (float)best1,
                           (best2 == MBOX) ? -1.0f : (float)best2,
                           (best3 == MBOX) ? -1.0f : (float)best3);
    *reinterpret_cast<float4*>(out + (size_t)b * N + i0) = o;
}

extern "C" void kernel_launch(void* const* d_in, const int* in_sizes, int n_in,
                              void* d_out, int out_size)
{
    const float* pts   = (const float*)d_in[0];
    const float* boxes = (const float*)d_in[1];
    float* out = (float*)d_out;

    const int N = out_size / BATCHES;                 // 65536
    const int grid = BATCHES * (N / (TPB * PPT));     // 4 * 64 = 256 blocks
    pib_fused<<<grid, TPB>>>(pts, boxes, out, N);
}

// round 10
// speedup vs baseline: 1.0035x; 1.0035x over previous
#include <cuda_runtime.h>

#define BATCHES 4
#define MBOX    128
#define TPB     256
#define PPT     2
#define GRIDW   32
#define NCELL   (GRIDW * GRIDW)
#define CAP     32    // smem list cap; overflow handled by brute-force fallback
#define BOXF    7     // floats per box

__global__ __launch_bounds__(TPB)
void pib_fused(const float* __restrict__ pts,
               const float* __restrict__ boxes,
               float* __restrict__ out,
               int N)
{
    // Preprocessed boxes:
    //   sA[m] = (cx, cy, cos, sin)
    //   sB[m] = (hx, hy, cz, hz)
    __shared__ float4 sA[MBOX];
    __shared__ float4 sB[MBOX];
    __shared__ int    cnt[NCELL];
    __shared__ unsigned char lst[NCELL][CAP];
    __shared__ float  sRaw[MBOX * BOXF];          // coalesced staging (3.5 KB)

    const int bpb = gridDim.x / BATCHES;     // 128
    const int b   = blockIdx.x / bpb;
    const int blk = blockIdx.x % bpb;
    const int t   = threadIdx.x;

    const float inv_cell = (float)GRIDW / 100.0f;   // 0.32
    const float org      = -50.0f;

    // ---- hoisted: issue point loads FIRST so their latency overlaps the
    //      table build (ptxas will not hoist LDG across the barrier itself).
    const int i0 = (blk * TPB + t) * PPT;
    const float2* p2 = reinterpret_cast<const float2*>(pts + ((size_t)b * N + i0) * 3);
    float2 qa = p2[0], qb = p2[1], qc = p2[2];

    // Zero counters (one STS.128 per thread) + coalesced box staging.
    {
        int4 z = make_int4(0, 0, 0, 0);
        reinterpret_cast<int4*>(cnt)[t] = z;      // NCELL/4 == TPB
        const float* src = boxes + (size_t)b * MBOX * BOXF;
        #pragma unroll
        for (int i = t; i < MBOX * BOXF; i += TPB)
            sRaw[i] = src[i];
    }
    __syncthreads();

    // ---- build: one thread per box, reading staged smem ----
    if (t < MBOX) {
        const float* bx = &sRaw[t * BOXF];
        float cx = bx[0], cy = bx[1], cz = bx[2];
        float hx = 0.5f * bx[3], hy = 0.5f * bx[4], hz = 0.5f * bx[5];
        float s, c;
        __sincosf(bx[6], &s, &c);
        sA[t] = make_float4(cx, cy, c, s);
        sB[t] = make_float4(hx, hy, cz, hz);

        // Conservative AABB of the rotated footprint, inflated well past
        // any fp rounding slack in the in-box test (~1e-5).
        float ac = fabsf(c), as = fabsf(s);
        float ex = hx * ac + hy * as + 1e-3f;
        float ey = hx * as + hy * ac + 1e-3f;

        int xlo = min(max((int)floorf((cx - ex - org) * inv_cell), 0), GRIDW - 1);
        int xhi = min(max((int)floorf((cx + ex - org) * inv_cell), 0), GRIDW - 1);
        int ylo = min(max((int)floorf((cy - ey - org) * inv_cell), 0), GRIDW - 1);
        int yhi = min(max((int)floorf((cy + ey - org) * inv_cell), 0), GRIDW - 1);

        for (int yy = ylo; yy <= yhi; ++yy)
            for (int xx = xlo; xx <= xhi; ++xx) {
                int cell = yy * GRIDW + xx;
                int p = atomicAdd(&cnt[cell], 1);
                if (p < CAP) lst[cell][p] = (unsigned char)t;
            }
    }

    // Cell indices computed from already-arrived registers (overlaps build).
    float x0 = qa.x, y0 = qa.y, z0 = qb.x;
    float x1 = qb.y, y1 = qc.x, z1 = qc.y;

    int ix0 = min(max((int)floorf((x0 - org) * inv_cell), 0), GRIDW - 1);
    int iy0 = min(max((int)floorf((y0 - org) * inv_cell), 0), GRIDW - 1);
    int ix1 = min(max((int)floorf((x1 - org) * inv_cell), 0), GRIDW - 1);
    int iy1 = min(max((int)floorf((y1 - org) * inv_cell), 0), GRIDW - 1);
    int cell0 = iy0 * GRIDW + ix0;
    int cell1 = iy1 * GRIDW + ix1;

    __syncthreads();

    // ---- query: two points per thread, interleaved, guard-free ----
    // Safety: evaluating the exact test against ANY box index is correct-
    // neutral (a true hit implies the box is in the point's cell list, so
    // min() is unchanged; a false hit contributes nothing). Hence entries
    // past a cell's count may be garbage; we only clamp to &127 for bounds.
    int n0 = cnt[cell0];
    int n1 = cnt[cell1];

    int l0 = (n0 <= CAP) ? n0 : 0;
    int l1 = (n1 <= CAP) ? n1 : 0;
    int nmax = (max(l0, l1) + 1) & ~1;            // <= CAP, multiple of 2

    int best0 = MBOX, best1 = MBOX;

    for (int j = 0; j < nmax; j += 2) {
        unsigned short u0 = *reinterpret_cast<const unsigned short*>(&lst[cell0][j]);
        unsigned short u1 = *reinterpret_cast<const unsigned short*>(&lst[cell1][j]);
        #pragma unroll
        for (int k = 0; k < 2; ++k) {
            {
                int m = (u0 >> (8 * k)) & 127;
                float4 A  = sA[m];
                float4 Bv = sB[m];
                float dx = x0 - A.x, dy = y0 - A.y, dz = z0 - Bv.z;
                float lx = dx * A.z + dy * A.w;
                float ly = dy * A.z - dx * A.w;
                bool in = (fabsf(lx) <= Bv.x) & (fabsf(ly) <= Bv.y) & (fabsf(dz) <= Bv.w);
                best0 = min(best0, in ? m : MBOX);
            }
            {
                int m = (u1 >> (8 * k)) & 127;
                float4 A  = sA[m];
                float4 Bv = sB[m];
                float dx = x1 - A.x, dy = y1 - A.y, dz = z1 - Bv.z;
                float lx = dx * A.z + dy * A.w;
                float ly = dy * A.z - dx * A.w;
                bool in = (fabsf(lx) <= Bv.x) & (fabsf(ly) <= Bv.y) & (fabsf(dz) <= Bv.w);
                best1 = min(best1, in ? m : MBOX);
            }
        }
    }

    // Structural overflow fallback: test every box (never skips a hit).
    if ((n0 > CAP) | (n1 > CAP)) {
        for (int m = 0; m < MBOX; ++m) {
            float4 A  = sA[m];
            float4 Bv = sB[m];
            if (n0 > CAP) {
                float dx = x0 - A.x, dy = y0 - A.y, dz = z0 - Bv.z;
                float lx = dx * A.z + dy * A.w;
                float ly = dy * A.z - dx * A.w;
                bool in = (fabsf(lx) <= Bv.x) & (fabsf(ly) <= Bv.y) & (fabsf(dz) <= Bv.w);
                best0 = min(best0, in ? m : MBOX);
            }
            if (n1 > CAP) {
                float dx = x1 - A.x, dy = y1 - A.y, dz = z1 - Bv.z;
                float lx = dx * A.z + dy * A.w;
                float ly = dy * A.z - dx * A.w;
                bool in = (fabsf(lx) <= Bv.x) & (fabsf(ly) <= Bv.y) & (fabsf(dz) <= Bv.w);
                best1 = min(best1, in ? m : MBOX);
            }
        }
    }

    float2 o = make_float2((best0 == MBOX) ? -1.0f : (float)best0,
                           (best1 == MBOX) ? -1.0f : (float)best1);
    *reinterpret_cast<float2*>(out + (size_t)b * N + i0) = o;
}

extern "C" void kernel_launch(void* const* d_in, const int* in_sizes, int n_in,
                              void* d_out, int out_size)
{
    const float* pts   = (const float*)d_in[0];
    const float* boxes = (const float*)d_in[1];
    float* out = (float*)d_out;

    const int N = out_size / BATCHES;                 // 65536
    const int grid = BATCHES * (N / (TPB * PPT));     // 4 * 128 = 512 blocks
    pib_fused<<<grid, TPB>>>(pts, boxes, out, N);
}

// round 11
// speedup vs baseline: 1.1055x; 1.1016x over previous
#include <cuda_runtime.h>

#define BATCHES 4
#define MBOX    128
#define TPB     256
#define PPT     2
#define GRIDW   32
#define NCELL   (GRIDW * GRIDW)
#define CAP     32    // smem list cap; overflow handled by brute-force fallback
#define BOXF    7     // floats per box

__global__ __launch_bounds__(TPB)
void pib_fused(const float* __restrict__ pts,
               const float* __restrict__ boxes,
               float* __restrict__ out,
               int N)
{
    // Preprocessed boxes:
    //   sA[m] = (cx, cy, cos, sin)
    //   sB[m] = (hx, hy, cz, hz)
    __shared__ float4 sA[MBOX];
    __shared__ float4 sB[MBOX];
    __shared__ int    cnt[NCELL];
    __shared__ unsigned char lst[NCELL][CAP];
    __shared__ float  sRaw[MBOX * BOXF];          // coalesced staging (3.5 KB)

    const int bpb = gridDim.x / BATCHES;     // 128
    const int b   = blockIdx.x / bpb;
    const int blk = blockIdx.x % bpb;
    const int t   = threadIdx.x;

    const float inv_cell  = (float)GRIDW / 100.0f;   // 0.32
    const float cell_sz   = 100.0f / (float)GRIDW;   // 3.125
    const float cell_half = 0.5f * cell_sz;          // 1.5625
    const float org       = -50.0f;

    // ---- hoisted: issue point loads FIRST so their latency overlaps the
    //      table build (ptxas will not hoist LDG across the barrier itself).
    const int i0 = (blk * TPB + t) * PPT;
    const float2* p2 = reinterpret_cast<const float2*>(pts + ((size_t)b * N + i0) * 3);
    float2 qa = p2[0], qb = p2[1], qc = p2[2];

    // Zero counters (one STS.128 per thread) + coalesced box staging.
    {
        int4 z = make_int4(0, 0, 0, 0);
        reinterpret_cast<int4*>(cnt)[t] = z;      // NCELL/4 == TPB
        const float* src = boxes + (size_t)b * MBOX * BOXF;
        #pragma unroll
        for (int i = t; i < MBOX * BOXF; i += TPB)
            sRaw[i] = src[i];
    }
    __syncthreads();

    // ---- build: TWO threads per box (t and t+128 split the row range).
    //      SAT-exact registration: AABB candidate cells are kept only if the
    //      rotated rect actually intersects the cell (two rect-axis tests;
    //      the x/y-axis tests are implied by the AABB range). A box that
    //      contains a point in cell C intersects C, and thresholds carry
    //      +1e-3 m slack >> fp error, so no containing box is ever dropped.
    {
        const int boxm = t & (MBOX - 1);          // t % 128
        const int halfid = t >> 7;                // 0: lower rows, 1: upper
        const float* bx = &sRaw[boxm * BOXF];
        float cx = bx[0], cy = bx[1], cz = bx[2];
        float hx = 0.5f * bx[3], hy = 0.5f * bx[4], hz = 0.5f * bx[5];
        float s, c;
        __sincosf(bx[6], &s, &c);
        if (halfid == 0) {
            sA[boxm] = make_float4(cx, cy, c, s);
            sB[boxm] = make_float4(hx, hy, cz, hz);
        }

        float ac = fabsf(c), as = fabsf(s);
        float ex = hx * ac + hy * as + 1e-3f;
        float ey = hx * as + hy * ac + 1e-3f;
        float rc = cell_half * (ac + as);         // cell half-extent on rect axes
        float thu = hx + rc + 1e-3f;
        float thv = hy + rc + 1e-3f;

        int xlo = min(max((int)floorf((cx - ex - org) * inv_cell), 0), GRIDW - 1);
        int xhi = min(max((int)floorf((cx + ex - org) * inv_cell), 0), GRIDW - 1);
        int ylo = min(max((int)floorf((cy - ey - org) * inv_cell), 0), GRIDW - 1);
        int yhi = min(max((int)floorf((cy + ey - org) * inv_cell), 0), GRIDW - 1);

        // Split rows between the two threads handling this box.
        int ymid = (ylo + yhi) >> 1;
        int y0 = halfid ? (ymid + 1) : ylo;
        int y1 = halfid ? yhi        : ymid;

        for (int yy = y0; yy <= y1; ++yy) {
            float qcy = org + ((float)yy + 0.5f) * cell_sz;
            float ddy = qcy - cy;
            for (int xx = xlo; xx <= xhi; ++xx) {
                float qcx = org + ((float)xx + 0.5f) * cell_sz;
                float ddx = qcx - cx;
                // Rect-axis SAT tests (u=(c,s), v=(-s,c)).
                float du = ddx * c + ddy * s;
                float dv = ddy * c - ddx * s;
                if ((fabsf(du) <= thu) & (fabsf(dv) <= thv)) {
                    int cell = yy * GRIDW + xx;
                    int p = atomicAdd(&cnt[cell], 1);
                    if (p < CAP) lst[cell][p] = (unsigned char)boxm;
                }
            }
        }
    }

    // Cell indices computed from already-arrived registers (overlaps build).
    float x0 = qa.x, y0 = qa.y, z0 = qb.x;
    float x1 = qb.y, y1 = qc.x, z1 = qc.y;

    int ix0 = min(max((int)floorf((x0 - org) * inv_cell), 0), GRIDW - 1);
    int iy0 = min(max((int)floorf((y0 - org) * inv_cell), 0), GRIDW - 1);
    int ix1 = min(max((int)floorf((x1 - org) * inv_cell), 0), GRIDW - 1);
    int iy1 = min(max((int)floorf((y1 - org) * inv_cell), 0), GRIDW - 1);
    int cell0 = iy0 * GRIDW + ix0;
    int cell1 = iy1 * GRIDW + ix1;

    __syncthreads();

    // ---- query: two points per thread, interleaved, guard-free ----
    // Safety: evaluating the exact test against ANY box index is correct-
    // neutral (a true hit implies the box is in the point's cell list, so
    // min() is unchanged; a false hit contributes nothing). Hence entries
    // past a cell's count may be garbage; we only clamp to &127 for bounds.
    int n0 = cnt[cell0];
    int n1 = cnt[cell1];

    int l0 = (n0 <= CAP) ? n0 : 0;
    int l1 = (n1 <= CAP) ? n1 : 0;
    int nmax = (max(l0, l1) + 1) & ~1;            // <= CAP, multiple of 2

    int best0 = MBOX, best1 = MBOX;

    for (int j = 0; j < nmax; j += 2) {
        unsigned short u0 = *reinterpret_cast<const unsigned short*>(&lst[cell0][j]);
        unsigned short u1 = *reinterpret_cast<const unsigned short*>(&lst[cell1][j]);
        #pragma unroll
        for (int k = 0; k < 2; ++k) {
            {
                int m = (u0 >> (8 * k)) & 127;
                float4 A  = sA[m];
                float4 Bv = sB[m];
                float dx = x0 - A.x, dy = y0 - A.y, dz = z0 - Bv.z;
                float lx = dx * A.z + dy * A.w;
                float ly = dy * A.z - dx * A.w;
                bool in = (fabsf(lx) <= Bv.x) & (fabsf(ly) <= Bv.y) & (fabsf(dz) <= Bv.w);
                best0 = min(best0, in ? m : MBOX);
            }
            {
                int m = (u1 >> (8 * k)) & 127;
                float4 A  = sA[m];
                float4 Bv = sB[m];
                float dx = x1 - A.x, dy = y1 - A.y, dz = z1 - Bv.z;
                float lx = dx * A.z + dy * A.w;
                float ly = dy * A.z - dx * A.w;
                bool in = (fabsf(lx) <= Bv.x) & (fabsf(ly) <= Bv.y) & (fabsf(dz) <= Bv.w);
                best1 = min(best1, in ? m : MBOX);
            }
        }
    }

    // Structural overflow fallback: test every box (never skips a hit).
    if ((n0 > CAP) | (n1 > CAP)) {
        for (int m = 0; m < MBOX; ++m) {
            float4 A  = sA[m];
            float4 Bv = sB[m];
            if (n0 > CAP) {
                float dx = x0 - A.x, dy = y0 - A.y, dz = z0 - Bv.z;
                float lx = dx * A.z + dy * A.w;
                float ly = dy * A.z - dx * A.w;
                bool in = (fabsf(lx) <= Bv.x) & (fabsf(ly) <= Bv.y) & (fabsf(dz) <= Bv.w);
                best0 = min(best0, in ? m : MBOX);
            }
            if (n1 > CAP) {
                float dx = x1 - A.x, dy = y1 - A.y, dz = z1 - Bv.z;
                float lx = dx * A.z + dy * A.w;
                float ly = dy * A.z - dx * A.w;
                bool in = (fabsf(lx) <= Bv.x) & (fabsf(ly) <= Bv.y) & (fabsf(dz) <= Bv.w);
                best1 = min(best1, in ? m : MBOX);
            }
        }
    }

    float2 o = make_float2((best0 == MBOX) ? -1.0f : (float)best0,
                           (best1 == MBOX) ? -1.0f : (float)best1);
    *reinterpret_cast<float2*>(out + (size_t)b * N + i0) = o;
}

extern "C" void kernel_launch(void* const* d_in, const int* in_sizes, int n_in,
                              void* d_out, int out_size)
{
    const float* pts   = (const float*)d_in[0];
    const float* boxes = (const float*)d_in[1];
    float* out = (float*)d_out;

    const int N = out_size / BATCHES;                 // 65536
    const int grid = BATCHES * (N / (TPB * PPT));     // 4 * 128 = 512 blocks
    pib_fused<<<grid, TPB>>>(pts, boxes, out, N);
}